// round 2
// baseline (speedup 1.0000x reference)
#include <cuda_runtime.h>
#include <cstdint>
#include <cstddef>

// Problem constants
#define K_SEQ    2048
#define K_BATCH  4
#define K_DM     1024
#define K_HEADS  16
#define K_HD     64
#define K_TOK    (K_BATCH * K_SEQ)   // 8192

// Scratch (device globals: allocation-free)
__device__ float g_qkv[(size_t)K_TOK * 3 * K_DM];   // [tok, 3*1024]
__device__ float g_ho [(size_t)K_TOK * K_DM];       // [tok, 1024] head outputs, (h,d) packed

// ---------------------------------------------------------------------------
// C[M,N] = A[M,K] @ B[N,K]^T + bias[N]
// 128x128 block tile, BK=8, 256 threads, 8x8 micro-tile (split quadrants).
// ---------------------------------------------------------------------------
__global__ __launch_bounds__(256)
void sgemm_nt(const float* __restrict__ A, const float* __restrict__ B,
              const float* __restrict__ bias, float* __restrict__ C,
              int M, int N, int K)
{
    __shared__ float As[8][128];   // [k][m]
    __shared__ float Bs[8][128];   // [k][n]

    const int tid = threadIdx.x;
    const int tx  = tid & 15;      // 0..15 -> cols
    const int ty  = tid >> 4;      // 0..15 -> rows
    const int m0  = blockIdx.y << 7;
    const int n0  = blockIdx.x << 7;

    const int lr = tid >> 1;        // 0..127 tile row for loads
    const int lc = (tid & 1) << 2;  // 0 or 4

    const float* Ag = A + (size_t)(m0 + lr) * K + lc;
    const float* Bg = B + (size_t)(n0 + lr) * K + lc;

    float acc[8][8];
#pragma unroll
    for (int i = 0; i < 8; i++)
#pragma unroll
        for (int j = 0; j < 8; j++) acc[i][j] = 0.f;

    for (int k0 = 0; k0 < K; k0 += 8) {
        float4 av = *(const float4*)(Ag + k0);
        float4 bv = *(const float4*)(Bg + k0);
        __syncthreads();
        As[lc + 0][lr] = av.x; As[lc + 1][lr] = av.y;
        As[lc + 2][lr] = av.z; As[lc + 3][lr] = av.w;
        Bs[lc + 0][lr] = bv.x; Bs[lc + 1][lr] = bv.y;
        Bs[lc + 2][lr] = bv.z; Bs[lc + 3][lr] = bv.w;
        __syncthreads();
#pragma unroll
        for (int kk = 0; kk < 8; kk++) {
            float a[8], b[8];
            *(float4*)(a)     = *(const float4*)&As[kk][ty * 4];
            *(float4*)(a + 4) = *(const float4*)&As[kk][64 + ty * 4];
            *(float4*)(b)     = *(const float4*)&Bs[kk][tx * 4];
            *(float4*)(b + 4) = *(const float4*)&Bs[kk][64 + tx * 4];
#pragma unroll
            for (int i = 0; i < 8; i++)
#pragma unroll
                for (int j = 0; j < 8; j++)
                    acc[i][j] = fmaf(a[i], b[j], acc[i][j]);
        }
    }

    float bb[8];
#pragma unroll
    for (int j = 0; j < 4; j++) {
        bb[j]     = bias[n0 + tx * 4 + j];
        bb[j + 4] = bias[n0 + 64 + tx * 4 + j];
    }
#pragma unroll
    for (int i = 0; i < 8; i++) {
        int row = m0 + ((i < 4) ? (ty * 4 + i) : (64 + ty * 4 + (i - 4)));
        float4 o0 = make_float4(acc[i][0] + bb[0], acc[i][1] + bb[1],
                                acc[i][2] + bb[2], acc[i][3] + bb[3]);
        float4 o1 = make_float4(acc[i][4] + bb[4], acc[i][5] + bb[5],
                                acc[i][6] + bb[6], acc[i][7] + bb[7]);
        *(float4*)&C[(size_t)row * N + n0 + tx * 4]      = o0;
        *(float4*)&C[(size_t)row * N + n0 + 64 + tx * 4] = o1;
    }
}

// ---------------------------------------------------------------------------
// Flash-style causal attention. One block per (b, h, 64-row q tile).
// Smem layouts chosen for conflict-free float4 inner-loop reads:
//   Qst [d][i]  64x64   Kst [d][j] 64x64   Vs [j][c] 64x64   Pst [j][i] 64x68
// ---------------------------------------------------------------------------
#define ATTN_SMEM_FLOATS (3 * 64 * 64 + 64 * 68)
#define ATTN_SMEM_BYTES  (ATTN_SMEM_FLOATS * 4)

__global__ __launch_bounds__(256)
void attn_kernel(const float* __restrict__ qkv, float* __restrict__ ho)
{
    extern __shared__ float sm[];
    float* Qst = sm;                 // [64][64]  (d-major)
    float* Kst = sm + 64 * 64;       // [64][64]  (d-major)
    float* Vs  = sm + 2 * 64 * 64;   // [64][64]  (token-major)
    float* Pst = sm + 3 * 64 * 64;   // [64][68]  (k-col-major)

    const int tid = threadIdx.x;
    const int tx  = tid & 15;        // S cols / O cols group
    const int ty  = tid >> 4;        // S rows group
    const int qt  = blockIdx.x;
    const int h   = blockIdx.y;
    const int b   = blockIdx.z;
    const int q0  = qt * 64;
    const float scale = 0.125f;      // 1/sqrt(64)

    const float* qg = qkv + (size_t)b * K_SEQ * 3 * K_DM + h * K_HD;
    const float* kg = qg + K_DM;
    const float* vg = qg + 2 * K_DM;

    const int lr = tid >> 2;            // token row 0..63
    const int lf = (tid & 3) * 16;      // d start 0/16/32/48

    // Load Q tile (transposed to d-major)
    {
        const float* src = qg + (size_t)(q0 + lr) * (3 * K_DM) + lf;
#pragma unroll
        for (int p = 0; p < 16; p += 4) {
            float4 v = *(const float4*)(src + p);
            Qst[(lf + p + 0) * 64 + lr] = v.x;
            Qst[(lf + p + 1) * 64 + lr] = v.y;
            Qst[(lf + p + 2) * 64 + lr] = v.z;
            Qst[(lf + p + 3) * 64 + lr] = v.w;
        }
    }

    float acc[4][4];
    float m_i[4], l_i[4];
#pragma unroll
    for (int i = 0; i < 4; i++) {
        m_i[i] = -1e30f; l_i[i] = 0.f;
#pragma unroll
        for (int c = 0; c < 4; c++) acc[i][c] = 0.f;
    }

    for (int kt = 0; kt <= qt; ++kt) {
        const int k0 = kt * 64;
        __syncthreads();   // prior phase-2 reads done (also covers Q-load on kt=0)
        {
            const float* ks = kg + (size_t)(k0 + lr) * (3 * K_DM) + lf;
            const float* vs = vg + (size_t)(k0 + lr) * (3 * K_DM) + lf;
#pragma unroll
            for (int p = 0; p < 16; p += 4) {
                float4 kv = *(const float4*)(ks + p);
                Kst[(lf + p + 0) * 64 + lr] = kv.x;
                Kst[(lf + p + 1) * 64 + lr] = kv.y;
                Kst[(lf + p + 2) * 64 + lr] = kv.z;
                Kst[(lf + p + 3) * 64 + lr] = kv.w;
                *(float4*)&Vs[lr * 64 + lf + p] = *(const float4*)(vs + p);
            }
        }
        __syncthreads();

        // Phase 1: S = Q K^T (4x4 per thread)
        float s[4][4];
#pragma unroll
        for (int i = 0; i < 4; i++)
#pragma unroll
            for (int j = 0; j < 4; j++) s[i][j] = 0.f;

#pragma unroll 8
        for (int d = 0; d < 64; ++d) {
            float4 qv = *(const float4*)&Qst[d * 64 + ty * 4];
            float4 kv = *(const float4*)&Kst[d * 64 + tx * 4];
            float qa[4] = {qv.x, qv.y, qv.z, qv.w};
            float ka[4] = {kv.x, kv.y, kv.z, kv.w};
#pragma unroll
            for (int i = 0; i < 4; i++)
#pragma unroll
                for (int j = 0; j < 4; j++)
                    s[i][j] = fmaf(qa[i], ka[j], s[i][j]);
        }

#pragma unroll
        for (int i = 0; i < 4; i++)
#pragma unroll
            for (int j = 0; j < 4; j++) s[i][j] *= scale;

        if (kt == qt) {   // causal mask inside diagonal tile
#pragma unroll
            for (int i = 0; i < 4; i++)
#pragma unroll
                for (int j = 0; j < 4; j++)
                    if (tx * 4 + j > ty * 4 + i) s[i][j] = -1e30f;
        }

        // Online softmax update (row stats shared across the 16 tx lanes)
#pragma unroll
        for (int i = 0; i < 4; i++) {
            float mr = fmaxf(fmaxf(s[i][0], s[i][1]), fmaxf(s[i][2], s[i][3]));
#pragma unroll
            for (int off = 1; off < 16; off <<= 1)
                mr = fmaxf(mr, __shfl_xor_sync(0xffffffffu, mr, off));
            float mnew  = fmaxf(m_i[i], mr);
            float alpha = __expf(m_i[i] - mnew);
            float rs = 0.f;
#pragma unroll
            for (int j = 0; j < 4; j++) {
                s[i][j] = __expf(s[i][j] - mnew);
                rs += s[i][j];
            }
#pragma unroll
            for (int off = 1; off < 16; off <<= 1)
                rs += __shfl_xor_sync(0xffffffffu, rs, off);
            l_i[i] = l_i[i] * alpha + rs;
            m_i[i] = mnew;
#pragma unroll
            for (int c = 0; c < 4; c++) acc[i][c] *= alpha;
        }

        // Store P transposed: Pst[j][i]
#pragma unroll
        for (int j = 0; j < 4; j++)
#pragma unroll
            for (int i = 0; i < 4; i++)
                Pst[(tx * 4 + j) * 68 + ty * 4 + i] = s[i][j];
        __syncthreads();

        // Phase 2: O += P @ V
#pragma unroll 8
        for (int j = 0; j < 64; ++j) {
            float4 pv = *(const float4*)&Pst[j * 68 + ty * 4];
            float4 vv = *(const float4*)&Vs[j * 64 + tx * 4];
            float pa[4] = {pv.x, pv.y, pv.z, pv.w};
            float va[4] = {vv.x, vv.y, vv.z, vv.w};
#pragma unroll
            for (int i = 0; i < 4; i++)
#pragma unroll
                for (int c = 0; c < 4; c++)
                    acc[i][c] = fmaf(pa[i], va[c], acc[i][c]);
        }
    }

    // Epilogue: normalize and write to [tok, h*64+d] layout
#pragma unroll
    for (int i = 0; i < 4; i++) {
        float inv = 1.f / l_i[i];
        size_t row = (size_t)b * K_SEQ + q0 + ty * 4 + i;
        float4 o = make_float4(acc[i][0] * inv, acc[i][1] * inv,
                               acc[i][2] * inv, acc[i][3] * inv);
        *(float4*)&ho[row * K_DM + h * K_HD + tx * 4] = o;
    }
}

// ---------------------------------------------------------------------------
extern "C" void kernel_launch(void* const* d_in, const int* in_sizes, int n_in,
                              void* d_out, int out_size)
{
    const float* x     = (const float*)d_in[0];
    const float* w_qkv = (const float*)d_in[1];
    const float* b_qkv = (const float*)d_in[2];
    const float* w_out = (const float*)d_in[3];
    const float* b_out = (const float*)d_in[4];
    float* out = (float*)d_out;

    float* qkv = nullptr;
    float* ho  = nullptr;
    cudaGetSymbolAddress((void**)&qkv, g_qkv);
    cudaGetSymbolAddress((void**)&ho,  g_ho);
    cudaFuncSetAttribute(attn_kernel,
                         cudaFuncAttributeMaxDynamicSharedMemorySize,
                         ATTN_SMEM_BYTES);

    // 1) qkv = x @ w_qkv^T + b_qkv     [8192, 3072]
    sgemm_nt<<<dim3((3 * K_DM) / 128, K_TOK / 128), 256>>>(
        x, w_qkv, b_qkv, qkv, K_TOK, 3 * K_DM, K_DM);

    // 2) causal flash attention -> head outputs [8192, 1024]
    attn_kernel<<<dim3(K_SEQ / 64, K_HEADS, K_BATCH), 256, ATTN_SMEM_BYTES>>>(
        qkv, ho);

    // 3) out = ho @ w_out^T + b_out    [8192, 1024]
    sgemm_nt<<<dim3(K_DM / 128, K_TOK / 128), 256>>>(
        ho, w_out, b_out, out, K_TOK, K_DM, K_DM);
}

// round 4
// speedup vs baseline: 1.5354x; 1.5354x over previous
#include <cuda_runtime.h>
#include <cstdint>
#include <cstddef>

// Problem constants
#define K_SEQ    2048
#define K_BATCH  4
#define K_DM     1024
#define K_HEADS  16
#define K_HD     64
#define K_TOK    (K_BATCH * K_SEQ)   // 8192

// Scratch (device globals: allocation-free)
__device__ float g_qkv[(size_t)K_TOK * 3 * K_DM];   // [tok, 3*1024]
__device__ float g_ho [(size_t)K_TOK * K_DM];       // [tok, 1024] head outputs

// ---------------------------------------------------------------------------
// tf32 helpers
// ---------------------------------------------------------------------------
__device__ __forceinline__ uint32_t f2tf(float f) {
    uint32_t u;
    asm("cvt.rna.tf32.f32 %0, %1;" : "=r"(u) : "f"(f));
    return u;
}

__device__ __forceinline__ void mma_tf32(float* d, const uint32_t* a, const uint32_t* b) {
    asm volatile(
        "mma.sync.aligned.m16n8k8.row.col.f32.tf32.tf32.f32 "
        "{%0,%1,%2,%3}, {%4,%5,%6,%7}, {%8,%9}, {%0,%1,%2,%3};"
        : "+f"(d[0]), "+f"(d[1]), "+f"(d[2]), "+f"(d[3])
        : "r"(a[0]), "r"(a[1]), "r"(a[2]), "r"(a[3]),
          "r"(b[0]), "r"(b[1]));
}

// ---------------------------------------------------------------------------
// C[M,N] = A[M,K] @ B[N,K]^T + bias[N], tf32 tensor cores.
// 128x128x32 CTA tile, 256 threads (8 warps of 64x32), smem stride 36
// (conflict-free fragment loads + aligned uint4 stores).
// ---------------------------------------------------------------------------
#define GS 36   // smem row stride in words

__global__ __launch_bounds__(256, 2)
void gemm_tf32(const float* __restrict__ A, const float* __restrict__ B,
               const float* __restrict__ bias, float* __restrict__ C,
               int M, int N, int K)
{
    __shared__ uint32_t As[128 * GS];
    __shared__ uint32_t Bs[128 * GS];

    const int tid   = threadIdx.x;
    const int lane  = tid & 31;
    const int wid   = tid >> 5;
    const int warpM = (wid >> 2) << 6;   // 0 / 64
    const int warpN = (wid & 3) << 5;    // 0 / 32 / 64 / 96
    const int m0 = blockIdx.y << 7;
    const int n0 = blockIdx.x << 7;
    const int fr = lane >> 2;            // 0..7
    const int fc = lane & 3;             // 0..3

    float acc[4][4][4];
#pragma unroll
    for (int mi = 0; mi < 4; mi++)
#pragma unroll
        for (int ni = 0; ni < 4; ni++)
#pragma unroll
            for (int r = 0; r < 4; r++) acc[mi][ni][r] = 0.f;

    const int grow = tid >> 3;           // 0..31 (rows grow, +32, +64, +96)
    const int gcol = (tid & 7) << 2;     // 0..28

    const float* Ag = A + (size_t)(m0 + grow) * K + gcol;
    const float* Bg = B + (size_t)(n0 + grow) * K + gcol;

    for (int k0 = 0; k0 < K; k0 += 32) {
        __syncthreads();
#pragma unroll
        for (int i = 0; i < 4; i++) {
            float4 av = *(const float4*)(Ag + (size_t)(i * 32) * K + k0);
            float4 bv = *(const float4*)(Bg + (size_t)(i * 32) * K + k0);
            uint4 at = make_uint4(f2tf(av.x), f2tf(av.y), f2tf(av.z), f2tf(av.w));
            uint4 bt = make_uint4(f2tf(bv.x), f2tf(bv.y), f2tf(bv.z), f2tf(bv.w));
            *(uint4*)&As[(grow + i * 32) * GS + gcol] = at;
            *(uint4*)&Bs[(grow + i * 32) * GS + gcol] = bt;
        }
        __syncthreads();

#pragma unroll
        for (int s = 0; s < 4; s++) {
            uint32_t a[4][4], b[4][2];
#pragma unroll
            for (int mi = 0; mi < 4; mi++) {
                const uint32_t* p = &As[(warpM + mi * 16 + fr) * GS + s * 8 + fc];
                a[mi][0] = p[0];
                a[mi][1] = p[8 * GS];
                a[mi][2] = p[4];
                a[mi][3] = p[8 * GS + 4];
            }
#pragma unroll
            for (int ni = 0; ni < 4; ni++) {
                const uint32_t* p = &Bs[(warpN + ni * 8 + fr) * GS + s * 8 + fc];
                b[ni][0] = p[0];
                b[ni][1] = p[4];
            }
#pragma unroll
            for (int mi = 0; mi < 4; mi++)
#pragma unroll
                for (int ni = 0; ni < 4; ni++)
                    mma_tf32(acc[mi][ni], a[mi], b[ni]);
        }
    }

    // Epilogue: bias + store (float2 per row fragment)
#pragma unroll
    for (int ni = 0; ni < 4; ni++) {
        int c = n0 + warpN + ni * 8 + fc * 2;
        float bb0 = bias[c], bb1 = bias[c + 1];
#pragma unroll
        for (int mi = 0; mi < 4; mi++) {
            int r = m0 + warpM + mi * 16 + fr;
            float2 v0 = make_float2(acc[mi][ni][0] + bb0, acc[mi][ni][1] + bb1);
            float2 v1 = make_float2(acc[mi][ni][2] + bb0, acc[mi][ni][3] + bb1);
            *(float2*)&C[(size_t)r * N + c]       = v0;
            *(float2*)&C[(size_t)(r + 8) * N + c] = v1;
        }
    }
}

// ---------------------------------------------------------------------------
// Flash-style causal attention (SIMT, unchanged this round).
// ---------------------------------------------------------------------------
#define ATTN_SMEM_FLOATS (3 * 64 * 64 + 64 * 68)
#define ATTN_SMEM_BYTES  (ATTN_SMEM_FLOATS * 4)

__global__ __launch_bounds__(256)
void attn_kernel(const float* __restrict__ qkv, float* __restrict__ ho)
{
    extern __shared__ float sm[];
    float* Qst = sm;                 // [64][64]  (d-major)
    float* Kst = sm + 64 * 64;       // [64][64]  (d-major)
    float* Vs  = sm + 2 * 64 * 64;   // [64][64]  (token-major)
    float* Pst = sm + 3 * 64 * 64;   // [64][68]  (k-col-major)

    const int tid = threadIdx.x;
    const int tx  = tid & 15;
    const int ty  = tid >> 4;
    const int qt  = blockIdx.x;
    const int h   = blockIdx.y;
    const int b   = blockIdx.z;
    const int q0  = qt * 64;
    const float scale = 0.125f;      // 1/sqrt(64)

    const float* qg = qkv + (size_t)b * K_SEQ * 3 * K_DM + h * K_HD;
    const float* kg = qg + K_DM;
    const float* vg = qg + 2 * K_DM;

    const int lr = tid >> 2;            // token row 0..63
    const int lf = (tid & 3) * 16;      // d start 0/16/32/48

    {
        const float* src = qg + (size_t)(q0 + lr) * (3 * K_DM) + lf;
#pragma unroll
        for (int p = 0; p < 16; p += 4) {
            float4 v = *(const float4*)(src + p);
            Qst[(lf + p + 0) * 64 + lr] = v.x;
            Qst[(lf + p + 1) * 64 + lr] = v.y;
            Qst[(lf + p + 2) * 64 + lr] = v.z;
            Qst[(lf + p + 3) * 64 + lr] = v.w;
        }
    }

    float acc[4][4];
    float m_i[4], l_i[4];
#pragma unroll
    for (int i = 0; i < 4; i++) {
        m_i[i] = -1e30f; l_i[i] = 0.f;
#pragma unroll
        for (int c = 0; c < 4; c++) acc[i][c] = 0.f;
    }

    for (int kt = 0; kt <= qt; ++kt) {
        const int k0 = kt * 64;
        __syncthreads();
        {
            const float* ks = kg + (size_t)(k0 + lr) * (3 * K_DM) + lf;
            const float* vs = vg + (size_t)(k0 + lr) * (3 * K_DM) + lf;
#pragma unroll
            for (int p = 0; p < 16; p += 4) {
                float4 kv = *(const float4*)(ks + p);
                Kst[(lf + p + 0) * 64 + lr] = kv.x;
                Kst[(lf + p + 1) * 64 + lr] = kv.y;
                Kst[(lf + p + 2) * 64 + lr] = kv.z;
                Kst[(lf + p + 3) * 64 + lr] = kv.w;
                *(float4*)&Vs[lr * 64 + lf + p] = *(const float4*)(vs + p);
            }
        }
        __syncthreads();

        float s[4][4];
#pragma unroll
        for (int i = 0; i < 4; i++)
#pragma unroll
            for (int j = 0; j < 4; j++) s[i][j] = 0.f;

#pragma unroll 8
        for (int d = 0; d < 64; ++d) {
            float4 qv = *(const float4*)&Qst[d * 64 + ty * 4];
            float4 kv = *(const float4*)&Kst[d * 64 + tx * 4];
            float qa[4] = {qv.x, qv.y, qv.z, qv.w};
            float ka[4] = {kv.x, kv.y, kv.z, kv.w};
#pragma unroll
            for (int i = 0; i < 4; i++)
#pragma unroll
                for (int j = 0; j < 4; j++)
                    s[i][j] = fmaf(qa[i], ka[j], s[i][j]);
        }

#pragma unroll
        for (int i = 0; i < 4; i++)
#pragma unroll
            for (int j = 0; j < 4; j++) s[i][j] *= scale;

        if (kt == qt) {
#pragma unroll
            for (int i = 0; i < 4; i++)
#pragma unroll
                for (int j = 0; j < 4; j++)
                    if (tx * 4 + j > ty * 4 + i) s[i][j] = -1e30f;
        }

#pragma unroll
        for (int i = 0; i < 4; i++) {
            float mr = fmaxf(fmaxf(s[i][0], s[i][1]), fmaxf(s[i][2], s[i][3]));
#pragma unroll
            for (int off = 1; off < 16; off <<= 1)
                mr = fmaxf(mr, __shfl_xor_sync(0xffffffffu, mr, off));
            float mnew  = fmaxf(m_i[i], mr);
            float alpha = __expf(m_i[i] - mnew);
            float rs = 0.f;
#pragma unroll
            for (int j = 0; j < 4; j++) {
                s[i][j] = __expf(s[i][j] - mnew);
                rs += s[i][j];
            }
#pragma unroll
            for (int off = 1; off < 16; off <<= 1)
                rs += __shfl_xor_sync(0xffffffffu, rs, off);
            l_i[i] = l_i[i] * alpha + rs;
            m_i[i] = mnew;
#pragma unroll
            for (int c = 0; c < 4; c++) acc[i][c] *= alpha;
        }

#pragma unroll
        for (int j = 0; j < 4; j++)
#pragma unroll
            for (int i = 0; i < 4; i++)
                Pst[(tx * 4 + j) * 68 + ty * 4 + i] = s[i][j];
        __syncthreads();

#pragma unroll 8
        for (int j = 0; j < 64; ++j) {
            float4 pv = *(const float4*)&Pst[j * 68 + ty * 4];
            float4 vv = *(const float4*)&Vs[j * 64 + tx * 4];
            float pa[4] = {pv.x, pv.y, pv.z, pv.w};
            float va[4] = {vv.x, vv.y, vv.z, vv.w};
#pragma unroll
            for (int i = 0; i < 4; i++)
#pragma unroll
                for (int c = 0; c < 4; c++)
                    acc[i][c] = fmaf(pa[i], va[c], acc[i][c]);
        }
    }

#pragma unroll
    for (int i = 0; i < 4; i++) {
        float inv = 1.f / l_i[i];
        size_t row = (size_t)b * K_SEQ + q0 + ty * 4 + i;
        float4 o = make_float4(acc[i][0] * inv, acc[i][1] * inv,
                               acc[i][2] * inv, acc[i][3] * inv);
        *(float4*)&ho[row * K_DM + h * K_HD + tx * 4] = o;
    }
}

// ---------------------------------------------------------------------------
extern "C" void kernel_launch(void* const* d_in, const int* in_sizes, int n_in,
                              void* d_out, int out_size)
{
    const float* x     = (const float*)d_in[0];
    const float* w_qkv = (const float*)d_in[1];
    const float* b_qkv = (const float*)d_in[2];
    const float* w_out = (const float*)d_in[3];
    const float* b_out = (const float*)d_in[4];
    float* out = (float*)d_out;

    float* qkv = nullptr;
    float* ho  = nullptr;
    cudaGetSymbolAddress((void**)&qkv, g_qkv);
    cudaGetSymbolAddress((void**)&ho,  g_ho);
    cudaFuncSetAttribute(attn_kernel,
                         cudaFuncAttributeMaxDynamicSharedMemorySize,
                         ATTN_SMEM_BYTES);

    // 1) qkv = x @ w_qkv^T + b_qkv     [8192, 3072]
    gemm_tf32<<<dim3((3 * K_DM) / 128, K_TOK / 128), 256>>>(
        x, w_qkv, b_qkv, qkv, K_TOK, 3 * K_DM, K_DM);

    // 2) causal flash attention -> head outputs [8192, 1024]
    attn_kernel<<<dim3(K_SEQ / 64, K_HEADS, K_BATCH), 256, ATTN_SMEM_BYTES>>>(
        qkv, ho);

    // 3) out = ho @ w_out^T + b_out    [8192, 1024]
    gemm_tf32<<<dim3(K_DM / 128, K_TOK / 128), 256>>>(
        ho, w_out, b_out, out, K_TOK, K_DM, K_DM);
}

// round 6
// speedup vs baseline: 2.2861x; 1.4889x over previous
#include <cuda_runtime.h>
#include <cstdint>
#include <cstddef>

// Problem constants
#define K_SEQ    2048
#define K_BATCH  4
#define K_DM     1024
#define K_HEADS  16
#define K_HD     64
#define K_TOK    (K_BATCH * K_SEQ)   // 8192

// Scratch (device globals: allocation-free)
__device__ float g_qkv[(size_t)K_TOK * 3 * K_DM];   // [tok, 3*1024]
__device__ float g_ho [(size_t)K_TOK * K_DM];       // [tok, 1024] head outputs

// ---------------------------------------------------------------------------
// tf32 helpers
// ---------------------------------------------------------------------------
__device__ __forceinline__ uint32_t f2tf(float f) {
    uint32_t u;
    asm("cvt.rna.tf32.f32 %0, %1;" : "=r"(u) : "f"(f));
    return u;
}

__device__ __forceinline__ void mma_tf32(float* d, const uint32_t* a, const uint32_t* b) {
    asm volatile(
        "mma.sync.aligned.m16n8k8.row.col.f32.tf32.tf32.f32 "
        "{%0,%1,%2,%3}, {%4,%5,%6,%7}, {%8,%9}, {%0,%1,%2,%3};"
        : "+f"(d[0]), "+f"(d[1]), "+f"(d[2]), "+f"(d[3])
        : "r"(a[0]), "r"(a[1]), "r"(a[2]), "r"(a[3]),
          "r"(b[0]), "r"(b[1]));
}

// ---------------------------------------------------------------------------
// C[M,N] = A[M,K] @ B[N,K]^T + bias[N], tf32 tensor cores.
// 128x128x32 CTA tile, 256 threads (8 warps of 64x32), smem stride 36.
// ---------------------------------------------------------------------------
#define GS 36   // smem row stride in words

__global__ __launch_bounds__(256, 2)
void gemm_tf32(const float* __restrict__ A, const float* __restrict__ B,
               const float* __restrict__ bias, float* __restrict__ C,
               int M, int N, int K)
{
    __shared__ uint32_t As[128 * GS];
    __shared__ uint32_t Bs[128 * GS];

    const int tid   = threadIdx.x;
    const int lane  = tid & 31;
    const int wid   = tid >> 5;
    const int warpM = (wid >> 2) << 6;   // 0 / 64
    const int warpN = (wid & 3) << 5;    // 0 / 32 / 64 / 96
    const int m0 = blockIdx.y << 7;
    const int n0 = blockIdx.x << 7;
    const int fr = lane >> 2;            // 0..7
    const int fc = lane & 3;             // 0..3

    float acc[4][4][4];
#pragma unroll
    for (int mi = 0; mi < 4; mi++)
#pragma unroll
        for (int ni = 0; ni < 4; ni++)
#pragma unroll
            for (int r = 0; r < 4; r++) acc[mi][ni][r] = 0.f;

    const int grow = tid >> 3;           // 0..31
    const int gcol = (tid & 7) << 2;     // 0..28

    const float* Ag = A + (size_t)(m0 + grow) * K + gcol;
    const float* Bg = B + (size_t)(n0 + grow) * K + gcol;

    for (int k0 = 0; k0 < K; k0 += 32) {
        __syncthreads();
#pragma unroll
        for (int i = 0; i < 4; i++) {
            float4 av = *(const float4*)(Ag + (size_t)(i * 32) * K + k0);
            float4 bv = *(const float4*)(Bg + (size_t)(i * 32) * K + k0);
            uint4 at = make_uint4(f2tf(av.x), f2tf(av.y), f2tf(av.z), f2tf(av.w));
            uint4 bt = make_uint4(f2tf(bv.x), f2tf(bv.y), f2tf(bv.z), f2tf(bv.w));
            *(uint4*)&As[(grow + i * 32) * GS + gcol] = at;
            *(uint4*)&Bs[(grow + i * 32) * GS + gcol] = bt;
        }
        __syncthreads();

#pragma unroll
        for (int s = 0; s < 4; s++) {
            uint32_t a[4][4], b[4][2];
#pragma unroll
            for (int mi = 0; mi < 4; mi++) {
                const uint32_t* p = &As[(warpM + mi * 16 + fr) * GS + s * 8 + fc];
                a[mi][0] = p[0];
                a[mi][1] = p[8 * GS];
                a[mi][2] = p[4];
                a[mi][3] = p[8 * GS + 4];
            }
#pragma unroll
            for (int ni = 0; ni < 4; ni++) {
                const uint32_t* p = &Bs[(warpN + ni * 8 + fr) * GS + s * 8 + fc];
                b[ni][0] = p[0];
                b[ni][1] = p[4];
            }
#pragma unroll
            for (int mi = 0; mi < 4; mi++)
#pragma unroll
                for (int ni = 0; ni < 4; ni++)
                    mma_tf32(acc[mi][ni], a[mi], b[ni]);
        }
    }

#pragma unroll
    for (int ni = 0; ni < 4; ni++) {
        int c = n0 + warpN + ni * 8 + fc * 2;
        float bb0 = bias[c], bb1 = bias[c + 1];
#pragma unroll
        for (int mi = 0; mi < 4; mi++) {
            int r = m0 + warpM + mi * 16 + fr;
            float2 v0 = make_float2(acc[mi][ni][0] + bb0, acc[mi][ni][1] + bb1);
            float2 v1 = make_float2(acc[mi][ni][2] + bb0, acc[mi][ni][3] + bb1);
            *(float2*)&C[(size_t)r * N + c]       = v0;
            *(float2*)&C[(size_t)(r + 8) * N + c] = v1;
        }
    }
}

// ---------------------------------------------------------------------------
// Tensor-core flash attention. One block per (b, h, 64-row q tile).
// 128 threads / 4 warps; warp w owns q-rows [16w, 16w+16) end-to-end.
// Smem (dynamic): Qs[64][68], Ks[64][68], Vt[64][68] (d-major), Ps[64][68].
// ---------------------------------------------------------------------------
#define AST 68
#define ATTN_SMEM_BYTES (4 * 64 * AST * 4)

__global__ __launch_bounds__(128, 3)
void attn_tc(const float* __restrict__ qkv, float* __restrict__ ho)
{
    extern __shared__ uint32_t dsm[];
    uint32_t* Qs = dsm;                 // [qrow][d]   A-operand layout
    uint32_t* Ks = dsm + 64 * AST;      // [krow][d]   B-operand layout
    uint32_t* Vt = dsm + 2 * 64 * AST;  // [d][krow]   B-operand layout for PV
    uint32_t* Ps = dsm + 3 * 64 * AST;  // [qrow][krow] A-operand layout

    const int tid  = threadIdx.x;
    const int lane = tid & 31;
    const int wid  = tid >> 5;
    const int wrow = wid << 4;          // 0/16/32/48
    const int fr   = lane >> 2;         // 0..7
    const int fc   = lane & 3;          // 0..3

    const int qt = blockIdx.x;
    const int h  = blockIdx.y;
    const int b  = blockIdx.z;
    const int q0 = qt * 64;

    const float* qg = qkv + (size_t)b * K_SEQ * 3 * K_DM + h * K_HD;
    const float* kg = qg + K_DM;
    const float* vg = qg + 2 * K_DM;

    // Tile-load indexing: row = tid>>1 (0..63), col base = (tid&1)*32
    const int lrow = tid >> 1;
    const int lcol = (tid & 1) << 5;

    // Load Q (pre-scaled by 1/sqrt(d)) into Qs[qrow][d]
    {
        const float* src = qg + (size_t)(q0 + lrow) * (3 * K_DM) + lcol;
#pragma unroll
        for (int p = 0; p < 32; p += 4) {
            float4 v = *(const float4*)(src + p);
            uint4 t = make_uint4(f2tf(v.x * 0.125f), f2tf(v.y * 0.125f),
                                 f2tf(v.z * 0.125f), f2tf(v.w * 0.125f));
            *(uint4*)&Qs[lrow * AST + lcol + p] = t;
        }
    }

    float o[8][4];
#pragma unroll
    for (int db = 0; db < 8; db++)
#pragma unroll
        for (int r = 0; r < 4; r++) o[db][r] = 0.f;
    float m_i[2] = {-1e30f, -1e30f};
    float l_i[2] = {0.f, 0.f};

    for (int kt = 0; kt <= qt; ++kt) {
        const int k0 = kt * 64;
        __syncthreads();   // all warps done reading previous K/V (covers Q load too)
        {
            const float* ks = kg + (size_t)(k0 + lrow) * (3 * K_DM) + lcol;
            const float* vs = vg + (size_t)(k0 + lrow) * (3 * K_DM) + lcol;
#pragma unroll
            for (int p = 0; p < 32; p += 4) {
                float4 kv = *(const float4*)(ks + p);
                uint4 t = make_uint4(f2tf(kv.x), f2tf(kv.y), f2tf(kv.z), f2tf(kv.w));
                *(uint4*)&Ks[lrow * AST + lcol + p] = t;
                float4 vv = *(const float4*)(vs + p);
                Vt[(lcol + p + 0) * AST + lrow] = f2tf(vv.x);
                Vt[(lcol + p + 1) * AST + lrow] = f2tf(vv.y);
                Vt[(lcol + p + 2) * AST + lrow] = f2tf(vv.z);
                Vt[(lcol + p + 3) * AST + lrow] = f2tf(vv.w);
            }
        }
        __syncthreads();

        // --- S = (Q/sqrt d) K^T : warp rows [wrow, wrow+16), cols 0..63 ---
        float s[8][4];
#pragma unroll
        for (int nb = 0; nb < 8; nb++)
#pragma unroll
            for (int r = 0; r < 4; r++) s[nb][r] = 0.f;

#pragma unroll
        for (int ks = 0; ks < 8; ks++) {
            uint32_t a[4];
            const uint32_t* pa = &Qs[(wrow + fr) * AST + ks * 8 + fc];
            a[0] = pa[0];
            a[1] = pa[8 * AST];
            a[2] = pa[4];
            a[3] = pa[8 * AST + 4];
#pragma unroll
            for (int nb = 0; nb < 8; nb++) {
                uint32_t bfr[2];
                const uint32_t* pb = &Ks[(nb * 8 + fr) * AST + ks * 8 + fc];
                bfr[0] = pb[0];
                bfr[1] = pb[4];
                mma_tf32(s[nb], a, bfr);
            }
        }

        // Causal mask inside the diagonal tile
        if (kt == qt) {
#pragma unroll
            for (int nb = 0; nb < 8; nb++) {
                int c0 = nb * 8 + 2 * fc;
#pragma unroll
                for (int rh = 0; rh < 2; rh++) {
                    int row = wrow + fr + rh * 8;
                    if (c0 > row)     s[nb][rh * 2 + 0] = -1e30f;
                    if (c0 + 1 > row) s[nb][rh * 2 + 1] = -1e30f;
                }
            }
        }

        // --- Online softmax: rows (wrow+fr) [rh=0] and (wrow+fr+8) [rh=1] ---
#pragma unroll
        for (int rh = 0; rh < 2; rh++) {
            float mr = -1e30f;
#pragma unroll
            for (int nb = 0; nb < 8; nb++)
                mr = fmaxf(mr, fmaxf(s[nb][rh * 2], s[nb][rh * 2 + 1]));
            mr = fmaxf(mr, __shfl_xor_sync(0xffffffffu, mr, 1));
            mr = fmaxf(mr, __shfl_xor_sync(0xffffffffu, mr, 2));
            float mnew  = fmaxf(m_i[rh], mr);
            float alpha = __expf(m_i[rh] - mnew);
            float rs = 0.f;
#pragma unroll
            for (int nb = 0; nb < 8; nb++) {
                float e0 = __expf(s[nb][rh * 2]     - mnew);
                float e1 = __expf(s[nb][rh * 2 + 1] - mnew);
                s[nb][rh * 2]     = e0;
                s[nb][rh * 2 + 1] = e1;
                rs += e0 + e1;
            }
            rs += __shfl_xor_sync(0xffffffffu, rs, 1);
            rs += __shfl_xor_sync(0xffffffffu, rs, 2);
            l_i[rh] = l_i[rh] * alpha + rs;
            m_i[rh] = mnew;
#pragma unroll
            for (int db = 0; db < 8; db++) {
                o[db][rh * 2]     *= alpha;
                o[db][rh * 2 + 1] *= alpha;
            }
        }

        // --- Re-fragment P via per-warp smem (accum layout -> A layout) ---
#pragma unroll
        for (int nb = 0; nb < 8; nb++) {
            uint2 v0 = make_uint2(f2tf(s[nb][0]), f2tf(s[nb][1]));
            uint2 v1 = make_uint2(f2tf(s[nb][2]), f2tf(s[nb][3]));
            *(uint2*)&Ps[(wrow + fr)     * AST + nb * 8 + 2 * fc] = v0;
            *(uint2*)&Ps[(wrow + fr + 8) * AST + nb * 8 + 2 * fc] = v1;
        }
        __syncwarp();

        // --- O += P @ V  (B operand = Vt[d][j]) ---
#pragma unroll
        for (int ks = 0; ks < 8; ks++) {
            uint32_t a[4];
            const uint32_t* pa = &Ps[(wrow + fr) * AST + ks * 8 + fc];
            a[0] = pa[0];
            a[1] = pa[8 * AST];
            a[2] = pa[4];
            a[3] = pa[8 * AST + 4];
#pragma unroll
            for (int db = 0; db < 8; db++) {
                uint32_t bfr[2];
                const uint32_t* pb = &Vt[(db * 8 + fr) * AST + ks * 8 + fc];
                bfr[0] = pb[0];
                bfr[1] = pb[4];
                mma_tf32(o[db], a, bfr);
            }
        }
        __syncwarp();   // Ps reads done before next iteration's stores
    }

    // Epilogue: normalize, write to [tok, h*64+d]
    float inv0 = 1.f / l_i[0];
    float inv1 = 1.f / l_i[1];
#pragma unroll
    for (int db = 0; db < 8; db++) {
        size_t r0 = (size_t)b * K_SEQ + q0 + wrow + fr;
        int c = h * K_HD + db * 8 + 2 * fc;
        *(float2*)&ho[r0 * K_DM + c] =
            make_float2(o[db][0] * inv0, o[db][1] * inv0);
        *(float2*)&ho[(r0 + 8) * K_DM + c] =
            make_float2(o[db][2] * inv1, o[db][3] * inv1);
    }
}

// ---------------------------------------------------------------------------
extern "C" void kernel_launch(void* const* d_in, const int* in_sizes, int n_in,
                              void* d_out, int out_size)
{
    const float* x     = (const float*)d_in[0];
    const float* w_qkv = (const float*)d_in[1];
    const float* b_qkv = (const float*)d_in[2];
    const float* w_out = (const float*)d_in[3];
    const float* b_out = (const float*)d_in[4];
    float* out = (float*)d_out;

    float* qkv = nullptr;
    float* ho  = nullptr;
    cudaGetSymbolAddress((void**)&qkv, g_qkv);
    cudaGetSymbolAddress((void**)&ho,  g_ho);
    cudaFuncSetAttribute(attn_tc,
                         cudaFuncAttributeMaxDynamicSharedMemorySize,
                         ATTN_SMEM_BYTES);

    // 1) qkv = x @ w_qkv^T + b_qkv     [8192, 3072]
    gemm_tf32<<<dim3((3 * K_DM) / 128, K_TOK / 128), 256>>>(
        x, w_qkv, b_qkv, qkv, K_TOK, 3 * K_DM, K_DM);

    // 2) causal flash attention (tensor cores) -> [8192, 1024]
    attn_tc<<<dim3(K_SEQ / 64, K_HEADS, K_BATCH), 128, ATTN_SMEM_BYTES>>>(
        qkv, ho);

    // 3) out = ho @ w_out^T + b_out    [8192, 1024]
    gemm_tf32<<<dim3(K_DM / 128, K_TOK / 128), 256>>>(
        ho, w_out, b_out, out, K_TOK, K_DM, K_DM);
}

// round 7
// speedup vs baseline: 3.0239x; 1.3228x over previous
#include <cuda_runtime.h>
#include <cstdint>
#include <cstddef>

// Problem constants
#define K_SEQ    2048
#define K_BATCH  4
#define K_DM     1024
#define K_HEADS  16
#define K_HD     64
#define K_TOK    (K_BATCH * K_SEQ)   // 8192

// Scratch (device globals: allocation-free)
__device__ float g_qkv[(size_t)K_TOK * 3 * K_DM];   // [tok, 3*1024]
__device__ float g_ho [(size_t)K_TOK * K_DM];       // [tok, 1024] head outputs

// ---------------------------------------------------------------------------
// tf32 helpers
// ---------------------------------------------------------------------------
__device__ __forceinline__ uint32_t f2tf(float f) {
    uint32_t u;
    asm("cvt.rna.tf32.f32 %0, %1;" : "=r"(u) : "f"(f));
    return u;
}

__device__ __forceinline__ void mma_tf32(float* d, const uint32_t* a, const uint32_t* b) {
    asm volatile(
        "mma.sync.aligned.m16n8k8.row.col.f32.tf32.tf32.f32 "
        "{%0,%1,%2,%3}, {%4,%5,%6,%7}, {%8,%9}, {%0,%1,%2,%3};"
        : "+f"(d[0]), "+f"(d[1]), "+f"(d[2]), "+f"(d[3])
        : "r"(a[0]), "r"(a[1]), "r"(a[2]), "r"(a[3]),
          "r"(b[0]), "r"(b[1]));
}

// ---------------------------------------------------------------------------
// C[M,N] = A[M,K] @ B[N,K]^T + bias[N], tf32 tensor cores. (unchanged)
// ---------------------------------------------------------------------------
#define GS 36   // smem row stride in words

__global__ __launch_bounds__(256, 2)
void gemm_tf32(const float* __restrict__ A, const float* __restrict__ B,
               const float* __restrict__ bias, float* __restrict__ C,
               int M, int N, int K)
{
    __shared__ uint32_t As[128 * GS];
    __shared__ uint32_t Bs[128 * GS];

    const int tid   = threadIdx.x;
    const int lane  = tid & 31;
    const int wid   = tid >> 5;
    const int warpM = (wid >> 2) << 6;   // 0 / 64
    const int warpN = (wid & 3) << 5;    // 0 / 32 / 64 / 96
    const int m0 = blockIdx.y << 7;
    const int n0 = blockIdx.x << 7;
    const int fr = lane >> 2;            // 0..7
    const int fc = lane & 3;             // 0..3

    float acc[4][4][4];
#pragma unroll
    for (int mi = 0; mi < 4; mi++)
#pragma unroll
        for (int ni = 0; ni < 4; ni++)
#pragma unroll
            for (int r = 0; r < 4; r++) acc[mi][ni][r] = 0.f;

    const int grow = tid >> 3;           // 0..31
    const int gcol = (tid & 7) << 2;     // 0..28

    const float* Ag = A + (size_t)(m0 + grow) * K + gcol;
    const float* Bg = B + (size_t)(n0 + grow) * K + gcol;

    for (int k0 = 0; k0 < K; k0 += 32) {
        __syncthreads();
#pragma unroll
        for (int i = 0; i < 4; i++) {
            float4 av = *(const float4*)(Ag + (size_t)(i * 32) * K + k0);
            float4 bv = *(const float4*)(Bg + (size_t)(i * 32) * K + k0);
            uint4 at = make_uint4(f2tf(av.x), f2tf(av.y), f2tf(av.z), f2tf(av.w));
            uint4 bt = make_uint4(f2tf(bv.x), f2tf(bv.y), f2tf(bv.z), f2tf(bv.w));
            *(uint4*)&As[(grow + i * 32) * GS + gcol] = at;
            *(uint4*)&Bs[(grow + i * 32) * GS + gcol] = bt;
        }
        __syncthreads();

#pragma unroll
        for (int s = 0; s < 4; s++) {
            uint32_t a[4][4], b[4][2];
#pragma unroll
            for (int mi = 0; mi < 4; mi++) {
                const uint32_t* p = &As[(warpM + mi * 16 + fr) * GS + s * 8 + fc];
                a[mi][0] = p[0];
                a[mi][1] = p[8 * GS];
                a[mi][2] = p[4];
                a[mi][3] = p[8 * GS + 4];
            }
#pragma unroll
            for (int ni = 0; ni < 4; ni++) {
                const uint32_t* p = &Bs[(warpN + ni * 8 + fr) * GS + s * 8 + fc];
                b[ni][0] = p[0];
                b[ni][1] = p[4];
            }
#pragma unroll
            for (int mi = 0; mi < 4; mi++)
#pragma unroll
                for (int ni = 0; ni < 4; ni++)
                    mma_tf32(acc[mi][ni], a[mi], b[ni]);
        }
    }

#pragma unroll
    for (int ni = 0; ni < 4; ni++) {
        int c = n0 + warpN + ni * 8 + fc * 2;
        float bb0 = bias[c], bb1 = bias[c + 1];
#pragma unroll
        for (int mi = 0; mi < 4; mi++) {
            int r = m0 + warpM + mi * 16 + fr;
            float2 v0 = make_float2(acc[mi][ni][0] + bb0, acc[mi][ni][1] + bb1);
            float2 v1 = make_float2(acc[mi][ni][2] + bb0, acc[mi][ni][3] + bb1);
            *(float2*)&C[(size_t)r * N + c]       = v0;
            *(float2*)&C[(size_t)(r + 8) * N + c] = v1;
        }
    }
}

// ---------------------------------------------------------------------------
// Tensor-core flash attention, v2.
// One block per (b, h, 128-row q tile). 256 threads / 8 warps; warp w owns
// q-rows [16w, 16w+16). K/V tiles are 64 rows, software-pipelined via
// register staging. Vt uses an XOR swizzle for conflict-free STS + LDS.
// Smem: Qs[128][68], Ks[64][68], Vt[64][68], Ps[128][68]  = 104448 B.
// ---------------------------------------------------------------------------
#define AST 68
#define Q_ROWS 128
#define ATTN_SMEM_BYTES ((Q_ROWS + 64 + 64 + Q_ROWS) * AST * 4)
#define VSW(d, j) ((d) * AST + ((j) ^ (((d) & 48) >> 1)))

__global__ __launch_bounds__(256, 2)
void attn_tc(const float* __restrict__ qkv, float* __restrict__ ho)
{
    extern __shared__ uint32_t dsm[];
    uint32_t* Qs = dsm;                        // [128][AST] A-operand layout
    uint32_t* Ks = dsm + Q_ROWS * AST;         // [64][AST]  B-operand layout
    uint32_t* Vt = dsm + (Q_ROWS + 64) * AST;  // [64][AST]  d-major, swizzled
    uint32_t* Ps = dsm + (Q_ROWS + 128) * AST; // [128][AST] A-operand layout

    const int tid  = threadIdx.x;
    const int lane = tid & 31;
    const int wid  = tid >> 5;          // 0..7
    const int wrow = wid << 4;          // 0..112
    const int fr   = lane >> 2;         // 0..7
    const int fc   = lane & 3;          // 0..3

    const int qt = (gridDim.x - 1) - blockIdx.x;   // heavy tiles first
    const int h  = blockIdx.y;
    const int b  = blockIdx.z;
    const int q0 = qt * Q_ROWS;
    const int ktmax = 2 * qt + 1;

    const float* qg = qkv + (size_t)b * K_SEQ * 3 * K_DM + h * K_HD;
    const float* kg = qg + K_DM;
    const float* vg = qg + 2 * K_DM;

    // --- Load Q (pre-scaled by 1/sqrt(d)) into Qs[qrow][d] ---
    {
        const int qr = tid >> 1;            // 0..127
        const int qc = (tid & 1) << 5;      // 0 / 32
        const float* src = qg + (size_t)(q0 + qr) * (3 * K_DM) + qc;
#pragma unroll
        for (int p = 0; p < 32; p += 4) {
            float4 v = *(const float4*)(src + p);
            uint4 t = make_uint4(f2tf(v.x * 0.125f), f2tf(v.y * 0.125f),
                                 f2tf(v.z * 0.125f), f2tf(v.w * 0.125f));
            *(uint4*)&Qs[qr * AST + qc + p] = t;
        }
    }

    // Staging indexing: row = tid>>2 (0..63), col base = (tid&3)*16
    const int lrow = tid >> 2;
    const int lcol = (tid & 3) << 4;

    // Prefetch tile 0 into registers
    float4 stgK[4], stgV[4];
    {
        const float* ks = kg + (size_t)lrow * (3 * K_DM) + lcol;
        const float* vs = vg + (size_t)lrow * (3 * K_DM) + lcol;
#pragma unroll
        for (int p = 0; p < 4; p++) {
            stgK[p] = *(const float4*)(ks + 4 * p);
            stgV[p] = *(const float4*)(vs + 4 * p);
        }
    }

    float o[8][4];
#pragma unroll
    for (int db = 0; db < 8; db++)
#pragma unroll
        for (int r = 0; r < 4; r++) o[db][r] = 0.f;
    float m_i[2] = {-1e30f, -1e30f};
    float l_i[2] = {0.f, 0.f};

    for (int kt = 0; kt <= ktmax; ++kt) {
        const int k0 = kt * 64;
        __syncthreads();   // previous tile's Ks/Vt/Ps reads done (covers Q store at kt=0)

        // Commit staged tile to smem (K row-major tf32, V transposed+swizzled)
#pragma unroll
        for (int p = 0; p < 4; p++) {
            uint4 t = make_uint4(f2tf(stgK[p].x), f2tf(stgK[p].y),
                                 f2tf(stgK[p].z), f2tf(stgK[p].w));
            *(uint4*)&Ks[lrow * AST + lcol + 4 * p] = t;
            const int d0 = lcol + 4 * p;
            Vt[VSW(d0 + 0, lrow)] = f2tf(stgV[p].x);
            Vt[VSW(d0 + 1, lrow)] = f2tf(stgV[p].y);
            Vt[VSW(d0 + 2, lrow)] = f2tf(stgV[p].z);
            Vt[VSW(d0 + 3, lrow)] = f2tf(stgV[p].w);
        }
        __syncthreads();

        const bool active = (k0 <= q0 + wrow + 15);

        if (active) {
            // --- S = (Q/sqrt d) K^T : warp rows [wrow, wrow+16), cols 0..63 ---
            float s[8][4];
#pragma unroll
            for (int nb = 0; nb < 8; nb++)
#pragma unroll
                for (int r = 0; r < 4; r++) s[nb][r] = 0.f;

#pragma unroll
            for (int ks = 0; ks < 8; ks++) {
                uint32_t a[4];
                const uint32_t* pa = &Qs[(wrow + fr) * AST + ks * 8 + fc];
                a[0] = pa[0];
                a[1] = pa[8 * AST];
                a[2] = pa[4];
                a[3] = pa[8 * AST + 4];
#pragma unroll
                for (int nb = 0; nb < 8; nb++) {
                    uint32_t bfr[2];
                    const uint32_t* pb = &Ks[(nb * 8 + fr) * AST + ks * 8 + fc];
                    bfr[0] = pb[0];
                    bfr[1] = pb[4];
                    mma_tf32(s[nb], a, bfr);
                }
            }

            // Causal mask (only when tile straddles this warp's diagonal)
            if (k0 + 63 > q0 + wrow) {
#pragma unroll
                for (int nb = 0; nb < 8; nb++) {
                    int c0 = k0 + nb * 8 + 2 * fc;
#pragma unroll
                    for (int rh = 0; rh < 2; rh++) {
                        int row = q0 + wrow + fr + rh * 8;
                        if (c0 > row)     s[nb][rh * 2 + 0] = -1e30f;
                        if (c0 + 1 > row) s[nb][rh * 2 + 1] = -1e30f;
                    }
                }
            }

            // --- Online softmax (rows wrow+fr and wrow+fr+8) ---
#pragma unroll
            for (int rh = 0; rh < 2; rh++) {
                float mr = -1e30f;
#pragma unroll
                for (int nb = 0; nb < 8; nb++)
                    mr = fmaxf(mr, fmaxf(s[nb][rh * 2], s[nb][rh * 2 + 1]));
                mr = fmaxf(mr, __shfl_xor_sync(0xffffffffu, mr, 1));
                mr = fmaxf(mr, __shfl_xor_sync(0xffffffffu, mr, 2));
                float mnew  = fmaxf(m_i[rh], mr);
                float alpha = __expf(m_i[rh] - mnew);
                float rs = 0.f;
#pragma unroll
                for (int nb = 0; nb < 8; nb++) {
                    float e0 = __expf(s[nb][rh * 2]     - mnew);
                    float e1 = __expf(s[nb][rh * 2 + 1] - mnew);
                    s[nb][rh * 2]     = e0;
                    s[nb][rh * 2 + 1] = e1;
                    rs += e0 + e1;
                }
                rs += __shfl_xor_sync(0xffffffffu, rs, 1);
                rs += __shfl_xor_sync(0xffffffffu, rs, 2);
                l_i[rh] = l_i[rh] * alpha + rs;
                m_i[rh] = mnew;
#pragma unroll
                for (int db = 0; db < 8; db++) {
                    o[db][rh * 2]     *= alpha;
                    o[db][rh * 2 + 1] *= alpha;
                }
            }

            // --- Re-fragment P via per-warp smem rows ---
#pragma unroll
            for (int nb = 0; nb < 8; nb++) {
                uint2 v0 = make_uint2(f2tf(s[nb][0]), f2tf(s[nb][1]));
                uint2 v1 = make_uint2(f2tf(s[nb][2]), f2tf(s[nb][3]));
                *(uint2*)&Ps[(wrow + fr)     * AST + nb * 8 + 2 * fc] = v0;
                *(uint2*)&Ps[(wrow + fr + 8) * AST + nb * 8 + 2 * fc] = v1;
            }
            __syncwarp();
        }

        // Prefetch next K/V tile while PV math runs (hides L2 latency)
        if (kt < ktmax) {
            const int kn = (kt + 1) * 64;
            const float* ks = kg + (size_t)(kn + lrow) * (3 * K_DM) + lcol;
            const float* vs = vg + (size_t)(kn + lrow) * (3 * K_DM) + lcol;
#pragma unroll
            for (int p = 0; p < 4; p++) {
                stgK[p] = *(const float4*)(ks + 4 * p);
                stgV[p] = *(const float4*)(vs + 4 * p);
            }
        }

        if (active) {
            // --- O += P @ V  (B operand from swizzled Vt) ---
#pragma unroll
            for (int ks = 0; ks < 8; ks++) {
                uint32_t a[4];
                const uint32_t* pa = &Ps[(wrow + fr) * AST + ks * 8 + fc];
                a[0] = pa[0];
                a[1] = pa[8 * AST];
                a[2] = pa[4];
                a[3] = pa[8 * AST + 4];
#pragma unroll
                for (int db = 0; db < 8; db++) {
                    uint32_t bfr[2];
                    const uint32_t* pb = &Vt[VSW(db * 8 + fr, ks * 8 + fc)];
                    bfr[0] = pb[0];
                    bfr[1] = pb[4];
                    mma_tf32(o[db], a, bfr);
                }
            }
            __syncwarp();   // Ps reads done before next iteration's stores
        }
    }

    // Epilogue: normalize, write to [tok, h*64+d]
    float inv0 = 1.f / l_i[0];
    float inv1 = 1.f / l_i[1];
#pragma unroll
    for (int db = 0; db < 8; db++) {
        size_t r0 = (size_t)b * K_SEQ + q0 + wrow + fr;
        int c = h * K_HD + db * 8 + 2 * fc;
        *(float2*)&ho[r0 * K_DM + c] =
            make_float2(o[db][0] * inv0, o[db][1] * inv0);
        *(float2*)&ho[(r0 + 8) * K_DM + c] =
            make_float2(o[db][2] * inv1, o[db][3] * inv1);
    }
}

// ---------------------------------------------------------------------------
extern "C" void kernel_launch(void* const* d_in, const int* in_sizes, int n_in,
                              void* d_out, int out_size)
{
    const float* x     = (const float*)d_in[0];
    const float* w_qkv = (const float*)d_in[1];
    const float* b_qkv = (const float*)d_in[2];
    const float* w_out = (const float*)d_in[3];
    const float* b_out = (const float*)d_in[4];
    float* out = (float*)d_out;

    float* qkv = nullptr;
    float* ho  = nullptr;
    cudaGetSymbolAddress((void**)&qkv, g_qkv);
    cudaGetSymbolAddress((void**)&ho,  g_ho);
    cudaFuncSetAttribute(attn_tc,
                         cudaFuncAttributeMaxDynamicSharedMemorySize,
                         ATTN_SMEM_BYTES);

    // 1) qkv = x @ w_qkv^T + b_qkv     [8192, 3072]
    gemm_tf32<<<dim3((3 * K_DM) / 128, K_TOK / 128), 256>>>(
        x, w_qkv, b_qkv, qkv, K_TOK, 3 * K_DM, K_DM);

    // 2) causal flash attention (tensor cores) -> [8192, 1024]
    attn_tc<<<dim3(K_SEQ / Q_ROWS, K_HEADS, K_BATCH), 256, ATTN_SMEM_BYTES>>>(
        qkv, ho);

    // 3) out = ho @ w_out^T + b_out    [8192, 1024]
    gemm_tf32<<<dim3(K_DM / 128, K_TOK / 128), 256>>>(
        ho, w_out, b_out, out, K_TOK, K_DM, K_DM);
}

// round 8
// speedup vs baseline: 3.1034x; 1.0263x over previous
#include <cuda_runtime.h>
#include <cstdint>
#include <cstddef>

// Problem constants
#define K_SEQ    2048
#define K_BATCH  4
#define K_DM     1024
#define K_HEADS  16
#define K_HD     64
#define K_TOK    (K_BATCH * K_SEQ)   // 8192

// Scratch (device globals: allocation-free)
__device__ float g_qkv[(size_t)K_TOK * 3 * K_DM];   // [tok, 3*1024]
__device__ float g_ho [(size_t)K_TOK * K_DM];       // [tok, 1024] head outputs

// ---------------------------------------------------------------------------
// tf32 helpers
// ---------------------------------------------------------------------------
__device__ __forceinline__ uint32_t f2tf(float f) {
    uint32_t u;
    asm("cvt.rna.tf32.f32 %0, %1;" : "=r"(u) : "f"(f));
    return u;
}

__device__ __forceinline__ void mma_tf32(float* d, const uint32_t* a, const uint32_t* b) {
    asm volatile(
        "mma.sync.aligned.m16n8k8.row.col.f32.tf32.tf32.f32 "
        "{%0,%1,%2,%3}, {%4,%5,%6,%7}, {%8,%9}, {%0,%1,%2,%3};"
        : "+f"(d[0]), "+f"(d[1]), "+f"(d[2]), "+f"(d[3])
        : "r"(a[0]), "r"(a[1]), "r"(a[2]), "r"(a[3]),
          "r"(b[0]), "r"(b[1]));
}

__device__ __forceinline__ uint32_t smem_u32(const void* p) {
    return (uint32_t)__cvta_generic_to_shared(p);
}

__device__ __forceinline__ void cp16(uint32_t dst, const void* src) {
    asm volatile("cp.async.cg.shared.global [%0], [%1], 16;"
                 :: "r"(dst), "l"(src));
}

// ---------------------------------------------------------------------------
// C[M,N] = A[M,K] @ B[N,K]^T + bias[N], tf32 tensor cores.
// v2: cp.async double-buffered smem pipeline; fp32 in smem, tf32 cvt at
// fragment load. 128x128x32 CTA tile, 256 threads, 8 warps of 64x32.
// ---------------------------------------------------------------------------
#define GS 36   // smem row stride in words
#define GEMM_BUF (128 * GS)
#define GEMM_SMEM_BYTES (4 * GEMM_BUF * 4)   // 2 bufs x (A+B) x 128*36 words

__global__ __launch_bounds__(256, 2)
void gemm_tf32(const float* __restrict__ A, const float* __restrict__ B,
               const float* __restrict__ bias, float* __restrict__ C,
               int M, int N, int K)
{
    extern __shared__ float gsm[];
    float* As = gsm;                  // [2][128*GS]
    float* Bs = gsm + 2 * GEMM_BUF;   // [2][128*GS]

    const int tid   = threadIdx.x;
    const int lane  = tid & 31;
    const int wid   = tid >> 5;
    const int warpM = (wid >> 2) << 6;   // 0 / 64
    const int warpN = (wid & 3) << 5;    // 0 / 32 / 64 / 96
    const int m0 = blockIdx.y << 7;
    const int n0 = blockIdx.x << 7;
    const int fr = lane >> 2;            // 0..7
    const int fc = lane & 3;             // 0..3

    float acc[4][4][4];
#pragma unroll
    for (int mi = 0; mi < 4; mi++)
#pragma unroll
        for (int ni = 0; ni < 4; ni++)
#pragma unroll
            for (int r = 0; r < 4; r++) acc[mi][ni][r] = 0.f;

    const int grow = tid >> 3;           // 0..31
    const int gcol = (tid & 7) << 2;     // 0..28

    const float* Ag = A + (size_t)(m0 + grow) * K + gcol;
    const float* Bg = B + (size_t)(n0 + grow) * K + gcol;

    const uint32_t aBase = smem_u32(As);
    const uint32_t bBase = smem_u32(Bs);

    const int NI = K >> 5;   // 32-wide k iterations

    // Prefetch iteration 0 into buffer 0
    {
#pragma unroll
        for (int i = 0; i < 4; i++) {
            uint32_t off = (uint32_t)(((grow + i * 32) * GS + gcol) * 4);
            cp16(aBase + off, Ag + (size_t)(i * 32) * K);
            cp16(bBase + off, Bg + (size_t)(i * 32) * K);
        }
        asm volatile("cp.async.commit_group;" ::: "memory");
    }

    for (int it = 0; it < NI; it++) {
        const int s = it & 1;

        // Prefetch next iteration into the other buffer
        if (it + 1 < NI) {
            const int k0n = (it + 1) << 5;
            const uint32_t sb = (uint32_t)((s ^ 1) * GEMM_BUF * 4);
#pragma unroll
            for (int i = 0; i < 4; i++) {
                uint32_t off = sb + (uint32_t)(((grow + i * 32) * GS + gcol) * 4);
                cp16(aBase + off, Ag + (size_t)(i * 32) * K + k0n);
                cp16(bBase + off, Bg + (size_t)(i * 32) * K + k0n);
            }
            asm volatile("cp.async.commit_group;" ::: "memory");
            asm volatile("cp.async.wait_group 1;" ::: "memory");
        } else {
            asm volatile("cp.async.wait_group 0;" ::: "memory");
        }
        __syncthreads();

        const float* Asb = As + s * GEMM_BUF;
        const float* Bsb = Bs + s * GEMM_BUF;

#pragma unroll
        for (int ks = 0; ks < 4; ks++) {
            uint32_t a[4][4], b[4][2];
#pragma unroll
            for (int mi = 0; mi < 4; mi++) {
                const float* p = &Asb[(warpM + mi * 16 + fr) * GS + ks * 8 + fc];
                a[mi][0] = f2tf(p[0]);
                a[mi][1] = f2tf(p[8 * GS]);
                a[mi][2] = f2tf(p[4]);
                a[mi][3] = f2tf(p[8 * GS + 4]);
            }
#pragma unroll
            for (int ni = 0; ni < 4; ni++) {
                const float* p = &Bsb[(warpN + ni * 8 + fr) * GS + ks * 8 + fc];
                b[ni][0] = f2tf(p[0]);
                b[ni][1] = f2tf(p[4]);
            }
#pragma unroll
            for (int mi = 0; mi < 4; mi++)
#pragma unroll
                for (int ni = 0; ni < 4; ni++)
                    mma_tf32(acc[mi][ni], a[mi], b[ni]);
        }
        __syncthreads();   // all reads of buf s done before it is re-prefetched
    }

    // Epilogue: bias + store
#pragma unroll
    for (int ni = 0; ni < 4; ni++) {
        int c = n0 + warpN + ni * 8 + fc * 2;
        float bb0 = bias[c], bb1 = bias[c + 1];
#pragma unroll
        for (int mi = 0; mi < 4; mi++) {
            int r = m0 + warpM + mi * 16 + fr;
            float2 v0 = make_float2(acc[mi][ni][0] + bb0, acc[mi][ni][1] + bb1);
            float2 v1 = make_float2(acc[mi][ni][2] + bb0, acc[mi][ni][3] + bb1);
            *(float2*)&C[(size_t)r * N + c]       = v0;
            *(float2*)&C[(size_t)(r + 8) * N + c] = v1;
        }
    }
}

// ---------------------------------------------------------------------------
// Tensor-core flash attention, v2 (unchanged from R7).
// ---------------------------------------------------------------------------
#define AST 68
#define Q_ROWS 128
#define ATTN_SMEM_BYTES ((Q_ROWS + 64 + 64 + Q_ROWS) * AST * 4)
#define VSW(d, j) ((d) * AST + ((j) ^ (((d) & 48) >> 1)))

__global__ __launch_bounds__(256, 2)
void attn_tc(const float* __restrict__ qkv, float* __restrict__ ho)
{
    extern __shared__ uint32_t dsm[];
    uint32_t* Qs = dsm;                        // [128][AST] A-operand layout
    uint32_t* Ks = dsm + Q_ROWS * AST;         // [64][AST]  B-operand layout
    uint32_t* Vt = dsm + (Q_ROWS + 64) * AST;  // [64][AST]  d-major, swizzled
    uint32_t* Ps = dsm + (Q_ROWS + 128) * AST; // [128][AST] A-operand layout

    const int tid  = threadIdx.x;
    const int lane = tid & 31;
    const int wid  = tid >> 5;          // 0..7
    const int wrow = wid << 4;          // 0..112
    const int fr   = lane >> 2;         // 0..7
    const int fc   = lane & 3;          // 0..3

    const int qt = (gridDim.x - 1) - blockIdx.x;   // heavy tiles first
    const int h  = blockIdx.y;
    const int b  = blockIdx.z;
    const int q0 = qt * Q_ROWS;
    const int ktmax = 2 * qt + 1;

    const float* qg = qkv + (size_t)b * K_SEQ * 3 * K_DM + h * K_HD;
    const float* kg = qg + K_DM;
    const float* vg = qg + 2 * K_DM;

    // --- Load Q (pre-scaled by 1/sqrt(d)) into Qs[qrow][d] ---
    {
        const int qr = tid >> 1;            // 0..127
        const int qc = (tid & 1) << 5;      // 0 / 32
        const float* src = qg + (size_t)(q0 + qr) * (3 * K_DM) + qc;
#pragma unroll
        for (int p = 0; p < 32; p += 4) {
            float4 v = *(const float4*)(src + p);
            uint4 t = make_uint4(f2tf(v.x * 0.125f), f2tf(v.y * 0.125f),
                                 f2tf(v.z * 0.125f), f2tf(v.w * 0.125f));
            *(uint4*)&Qs[qr * AST + qc + p] = t;
        }
    }

    // Staging indexing: row = tid>>2 (0..63), col base = (tid&3)*16
    const int lrow = tid >> 2;
    const int lcol = (tid & 3) << 4;

    // Prefetch tile 0 into registers
    float4 stgK[4], stgV[4];
    {
        const float* ks = kg + (size_t)lrow * (3 * K_DM) + lcol;
        const float* vs = vg + (size_t)lrow * (3 * K_DM) + lcol;
#pragma unroll
        for (int p = 0; p < 4; p++) {
            stgK[p] = *(const float4*)(ks + 4 * p);
            stgV[p] = *(const float4*)(vs + 4 * p);
        }
    }

    float o[8][4];
#pragma unroll
    for (int db = 0; db < 8; db++)
#pragma unroll
        for (int r = 0; r < 4; r++) o[db][r] = 0.f;
    float m_i[2] = {-1e30f, -1e30f};
    float l_i[2] = {0.f, 0.f};

    for (int kt = 0; kt <= ktmax; ++kt) {
        const int k0 = kt * 64;
        __syncthreads();   // previous tile's Ks/Vt/Ps reads done (covers Q store at kt=0)

        // Commit staged tile to smem (K row-major tf32, V transposed+swizzled)
#pragma unroll
        for (int p = 0; p < 4; p++) {
            uint4 t = make_uint4(f2tf(stgK[p].x), f2tf(stgK[p].y),
                                 f2tf(stgK[p].z), f2tf(stgK[p].w));
            *(uint4*)&Ks[lrow * AST + lcol + 4 * p] = t;
            const int d0 = lcol + 4 * p;
            Vt[VSW(d0 + 0, lrow)] = f2tf(stgV[p].x);
            Vt[VSW(d0 + 1, lrow)] = f2tf(stgV[p].y);
            Vt[VSW(d0 + 2, lrow)] = f2tf(stgV[p].z);
            Vt[VSW(d0 + 3, lrow)] = f2tf(stgV[p].w);
        }
        __syncthreads();

        const bool active = (k0 <= q0 + wrow + 15);

        if (active) {
            // --- S = (Q/sqrt d) K^T ---
            float s[8][4];
#pragma unroll
            for (int nb = 0; nb < 8; nb++)
#pragma unroll
                for (int r = 0; r < 4; r++) s[nb][r] = 0.f;

#pragma unroll
            for (int ks = 0; ks < 8; ks++) {
                uint32_t a[4];
                const uint32_t* pa = &Qs[(wrow + fr) * AST + ks * 8 + fc];
                a[0] = pa[0];
                a[1] = pa[8 * AST];
                a[2] = pa[4];
                a[3] = pa[8 * AST + 4];
#pragma unroll
                for (int nb = 0; nb < 8; nb++) {
                    uint32_t bfr[2];
                    const uint32_t* pb = &Ks[(nb * 8 + fr) * AST + ks * 8 + fc];
                    bfr[0] = pb[0];
                    bfr[1] = pb[4];
                    mma_tf32(s[nb], a, bfr);
                }
            }

            // Causal mask (only when tile straddles this warp's diagonal)
            if (k0 + 63 > q0 + wrow) {
#pragma unroll
                for (int nb = 0; nb < 8; nb++) {
                    int c0 = k0 + nb * 8 + 2 * fc;
#pragma unroll
                    for (int rh = 0; rh < 2; rh++) {
                        int row = q0 + wrow + fr + rh * 8;
                        if (c0 > row)     s[nb][rh * 2 + 0] = -1e30f;
                        if (c0 + 1 > row) s[nb][rh * 2 + 1] = -1e30f;
                    }
                }
            }

            // --- Online softmax ---
#pragma unroll
            for (int rh = 0; rh < 2; rh++) {
                float mr = -1e30f;
#pragma unroll
                for (int nb = 0; nb < 8; nb++)
                    mr = fmaxf(mr, fmaxf(s[nb][rh * 2], s[nb][rh * 2 + 1]));
                mr = fmaxf(mr, __shfl_xor_sync(0xffffffffu, mr, 1));
                mr = fmaxf(mr, __shfl_xor_sync(0xffffffffu, mr, 2));
                float mnew  = fmaxf(m_i[rh], mr);
                float alpha = __expf(m_i[rh] - mnew);
                float rs = 0.f;
#pragma unroll
                for (int nb = 0; nb < 8; nb++) {
                    float e0 = __expf(s[nb][rh * 2]     - mnew);
                    float e1 = __expf(s[nb][rh * 2 + 1] - mnew);
                    s[nb][rh * 2]     = e0;
                    s[nb][rh * 2 + 1] = e1;
                    rs += e0 + e1;
                }
                rs += __shfl_xor_sync(0xffffffffu, rs, 1);
                rs += __shfl_xor_sync(0xffffffffu, rs, 2);
                l_i[rh] = l_i[rh] * alpha + rs;
                m_i[rh] = mnew;
#pragma unroll
                for (int db = 0; db < 8; db++) {
                    o[db][rh * 2]     *= alpha;
                    o[db][rh * 2 + 1] *= alpha;
                }
            }

            // --- Re-fragment P via per-warp smem rows ---
#pragma unroll
            for (int nb = 0; nb < 8; nb++) {
                uint2 v0 = make_uint2(f2tf(s[nb][0]), f2tf(s[nb][1]));
                uint2 v1 = make_uint2(f2tf(s[nb][2]), f2tf(s[nb][3]));
                *(uint2*)&Ps[(wrow + fr)     * AST + nb * 8 + 2 * fc] = v0;
                *(uint2*)&Ps[(wrow + fr + 8) * AST + nb * 8 + 2 * fc] = v1;
            }
            __syncwarp();
        }

        // Prefetch next K/V tile while PV math runs (hides L2 latency)
        if (kt < ktmax) {
            const int kn = (kt + 1) * 64;
            const float* ks = kg + (size_t)(kn + lrow) * (3 * K_DM) + lcol;
            const float* vs = vg + (size_t)(kn + lrow) * (3 * K_DM) + lcol;
#pragma unroll
            for (int p = 0; p < 4; p++) {
                stgK[p] = *(const float4*)(ks + 4 * p);
                stgV[p] = *(const float4*)(vs + 4 * p);
            }
        }

        if (active) {
            // --- O += P @ V ---
#pragma unroll
            for (int ks = 0; ks < 8; ks++) {
                uint32_t a[4];
                const uint32_t* pa = &Ps[(wrow + fr) * AST + ks * 8 + fc];
                a[0] = pa[0];
                a[1] = pa[8 * AST];
                a[2] = pa[4];
                a[3] = pa[8 * AST + 4];
#pragma unroll
                for (int db = 0; db < 8; db++) {
                    uint32_t bfr[2];
                    const uint32_t* pb = &Vt[VSW(db * 8 + fr, ks * 8 + fc)];
                    bfr[0] = pb[0];
                    bfr[1] = pb[4];
                    mma_tf32(o[db], a, bfr);
                }
            }
            __syncwarp();
        }
    }

    // Epilogue: normalize, write to [tok, h*64+d]
    float inv0 = 1.f / l_i[0];
    float inv1 = 1.f / l_i[1];
#pragma unroll
    for (int db = 0; db < 8; db++) {
        size_t r0 = (size_t)b * K_SEQ + q0 + wrow + fr;
        int c = h * K_HD + db * 8 + 2 * fc;
        *(float2*)&ho[r0 * K_DM + c] =
            make_float2(o[db][0] * inv0, o[db][1] * inv0);
        *(float2*)&ho[(r0 + 8) * K_DM + c] =
            make_float2(o[db][2] * inv1, o[db][3] * inv1);
    }
}

// ---------------------------------------------------------------------------
extern "C" void kernel_launch(void* const* d_in, const int* in_sizes, int n_in,
                              void* d_out, int out_size)
{
    const float* x     = (const float*)d_in[0];
    const float* w_qkv = (const float*)d_in[1];
    const float* b_qkv = (const float*)d_in[2];
    const float* w_out = (const float*)d_in[3];
    const float* b_out = (const float*)d_in[4];
    float* out = (float*)d_out;

    float* qkv = nullptr;
    float* ho  = nullptr;
    cudaGetSymbolAddress((void**)&qkv, g_qkv);
    cudaGetSymbolAddress((void**)&ho,  g_ho);
    cudaFuncSetAttribute(gemm_tf32,
                         cudaFuncAttributeMaxDynamicSharedMemorySize,
                         GEMM_SMEM_BYTES);
    cudaFuncSetAttribute(attn_tc,
                         cudaFuncAttributeMaxDynamicSharedMemorySize,
                         ATTN_SMEM_BYTES);

    // 1) qkv = x @ w_qkv^T + b_qkv     [8192, 3072]
    gemm_tf32<<<dim3((3 * K_DM) / 128, K_TOK / 128), 256, GEMM_SMEM_BYTES>>>(
        x, w_qkv, b_qkv, qkv, K_TOK, 3 * K_DM, K_DM);

    // 2) causal flash attention (tensor cores) -> [8192, 1024]
    attn_tc<<<dim3(K_SEQ / Q_ROWS, K_HEADS, K_BATCH), 256, ATTN_SMEM_BYTES>>>(
        qkv, ho);

    // 3) out = ho @ w_out^T + b_out    [8192, 1024]
    gemm_tf32<<<dim3(K_DM / 128, K_TOK / 128), 256, GEMM_SMEM_BYTES>>>(
        ho, w_out, b_out, out, K_TOK, K_DM, K_DM);
}